// round 4
// baseline (speedup 1.0000x reference)
#include <cuda_runtime.h>
#include <math.h>

#define B_ 8
#define L_ 1024
#define D_ 256
#define U_ 256

typedef unsigned long long ull;

// ---------------- scratch (device globals; no allocation allowed) ----------
__device__ float g_EW[D_ * U_];          // E @ Wx            (256 KB)
__device__ float g_rnorm[B_ * L_];       // 1/max(rowsum,eps) (32 KB)
__device__ float g_t[B_ * L_ * U_];      // (seq@EW)*rnorm    (8 MB)
__device__ float g_xproj[B_ * L_ * U_];  // G^T @ t           (8 MB)

// ---------------- packed f32x2 helpers (sm_103a) ----------------------------
__device__ __forceinline__ ull pk2(float lo, float hi) {
    ull r; asm("mov.b64 %0,{%1,%2};" : "=l"(r) : "f"(lo), "f"(hi)); return r;
}
__device__ __forceinline__ void ffma2(ull& d, ull a, ull b) {
    asm("fma.rn.f32x2 %0,%1,%2,%0;" : "+l"(d) : "l"(a), "l"(b));
}
__device__ __forceinline__ float2 up2(ull a) {
    float lo, hi; asm("mov.b64 {%0,%1},%2;" : "=f"(lo), "=f"(hi) : "l"(a));
    float2 r; r.x = lo; r.y = hi; return r;
}
// tanh(z) = 1 - 2/(1+exp(2z)) with MUFU ex2/rcp (rel err ~1e-6; validated R3)
__device__ __forceinline__ float fast_tanh(float z) {
    float t2 = z * 2.885390081777927f;  // 2*log2(e)
    float ex; asm("ex2.approx.f32 %0,%1;" : "=f"(ex) : "f"(t2));
    float den = ex + 1.0f;
    float rc; asm("rcp.approx.f32 %0,%1;" : "=f"(rc) : "f"(den));
    return fmaf(-2.0f, rc, 1.0f);
}

// ---------------- 1) rnorm[b,l] = 1 / max(sum_m graph[b,l,m], 1e-7) ---------
__global__ __launch_bounds__(256) void norm_kernel(const float* __restrict__ graph,
                                                   float* __restrict__ rnorm) {
    int warp = (blockIdx.x * blockDim.x + threadIdx.x) >> 5;
    int lane = threadIdx.x & 31;
    if (warp >= B_ * L_) return;
    const float4* row = (const float4*)(graph + (size_t)warp * L_);
    float s = 0.f;
#pragma unroll
    for (int i = lane; i < L_ / 4; i += 32) {
        float4 v = row[i];
        s += (v.x + v.y) + (v.z + v.w);
    }
#pragma unroll
    for (int o = 16; o; o >>= 1) s += __shfl_xor_sync(0xffffffffu, s, o);
    if (lane == 0) rnorm[warp] = 1.f / fmaxf(s, 1e-7f);
}

// ---------------- 2) GEMM NN: C[M,N] = A[M,K] @ B[K,N] (* rowscale) ---------
// 64x128 tile, BK=16, 256 threads, 4x8 micro-tile, 2 CTAs/SM.
__global__ __launch_bounds__(256, 2) void gemm_nn(const float* __restrict__ A,
                                                  const float* __restrict__ Bm,
                                                  float* __restrict__ C, int K,
                                                  const float* __restrict__ rowscale) {
    __shared__ float As[2][16][64];
    __shared__ float Bs[2][16][128];
    const int N = 256;
    const int m0 = blockIdx.y * 64, n0 = blockIdx.x * 128;
    const int t = threadIdx.x;
    const int tx = t & 15, ty = t >> 4;

    ull acc[4][4];
#pragma unroll
    for (int i = 0; i < 4; i++)
#pragma unroll
        for (int j = 0; j < 4; j++) acc[i][j] = 0ull;

    // A tile: 64x16 = 256 float4, 1 per thread
    const int am = t >> 2, akg = t & 3;
    // B tile: 16x128 = 512 float4, 2 per thread
    int bkk[2], bng[2];
#pragma unroll
    for (int i = 0; i < 2; i++) {
        int f4 = t + i * 256;
        bkk[i] = f4 >> 5; bng[i] = f4 & 31;
    }

    float4 ra, rb[2];
    ra = *(const float4*)(A + (size_t)(m0 + am) * K + akg * 4);
#pragma unroll
    for (int i = 0; i < 2; i++)
        rb[i] = *(const float4*)(Bm + (size_t)bkk[i] * N + n0 + bng[i] * 4);

    int cur = 0;
    for (int k0 = 0; k0 < K; k0 += 16) {
        As[cur][akg * 4 + 0][am] = ra.x;
        As[cur][akg * 4 + 1][am] = ra.y;
        As[cur][akg * 4 + 2][am] = ra.z;
        As[cur][akg * 4 + 3][am] = ra.w;
#pragma unroll
        for (int i = 0; i < 2; i++)
            *(float4*)&Bs[cur][bkk[i]][bng[i] * 4] = rb[i];
        __syncthreads();
        if (k0 + 16 < K) {
            ra = *(const float4*)(A + (size_t)(m0 + am) * K + k0 + 16 + akg * 4);
#pragma unroll
            for (int i = 0; i < 2; i++)
                rb[i] = *(const float4*)(Bm + (size_t)(k0 + 16 + bkk[i]) * N + n0 + bng[i] * 4);
        }
#pragma unroll
        for (int kk = 0; kk < 16; kk++) {
            float4 a = *(float4*)&As[cur][kk][ty * 4];
            float4 b0 = *(float4*)&Bs[cur][kk][tx * 8];
            float4 b1 = *(float4*)&Bs[cur][kk][tx * 8 + 4];
            ull bp0 = pk2(b0.x, b0.y), bp1 = pk2(b0.z, b0.w);
            ull bp2 = pk2(b1.x, b1.y), bp3 = pk2(b1.z, b1.w);
            float av[4] = {a.x, a.y, a.z, a.w};
#pragma unroll
            for (int i = 0; i < 4; i++) {
                ull ad = pk2(av[i], av[i]);
                ffma2(acc[i][0], ad, bp0);
                ffma2(acc[i][1], ad, bp1);
                ffma2(acc[i][2], ad, bp2);
                ffma2(acc[i][3], ad, bp3);
            }
        }
        cur ^= 1;
    }
#pragma unroll
    for (int i = 0; i < 4; i++) {
        int row = m0 + ty * 4 + i;
        float sc = rowscale ? rowscale[row] : 1.f;
        float2 v0 = up2(acc[i][0]), v1 = up2(acc[i][1]);
        float2 v2 = up2(acc[i][2]), v3 = up2(acc[i][3]);
        float4 o0 = make_float4(v0.x * sc, v0.y * sc, v1.x * sc, v1.y * sc);
        float4 o1 = make_float4(v2.x * sc, v2.y * sc, v3.x * sc, v3.y * sc);
        *(float4*)(C + (size_t)row * N + n0 + tx * 8) = o0;
        *(float4*)(C + (size_t)row * N + n0 + tx * 8 + 4) = o1;
    }
}

// ---------------- 3) GEMM TN (per batch): C[m,u] = sum_l G[l,m] * t[l,u] ----
// 64x128 tile, BK=16, 256 threads, 4x8 micro-tile, 2 CTAs/SM.
__global__ __launch_bounds__(256, 2) void gemm_tn(const float* __restrict__ A,
                                                  const float* __restrict__ Bm,
                                                  float* __restrict__ C) {
    __shared__ float As[2][16][64];
    __shared__ float Bs[2][16][128];
    const int N = 256, K = L_, lda = L_;
    const int b = blockIdx.z;
    A += (size_t)b * L_ * L_;
    Bm += (size_t)b * L_ * U_;
    C += (size_t)b * L_ * U_;
    const int m0 = blockIdx.y * 64, n0 = blockIdx.x * 128;
    const int t = threadIdx.x;
    const int tx = t & 15, ty = t >> 4;

    ull acc[4][4];
#pragma unroll
    for (int i = 0; i < 4; i++)
#pragma unroll
        for (int j = 0; j < 4; j++) acc[i][j] = 0ull;

    // A tile: 16x64 = 256 float4, 1 per thread (A is k-major over l)
    const int akk = t >> 4, ag = t & 15;
    // B tile: 16x128 = 512 float4, 2 per thread
    int bkk[2], bng[2];
#pragma unroll
    for (int i = 0; i < 2; i++) {
        int f4 = t + i * 256;
        bkk[i] = f4 >> 5; bng[i] = f4 & 31;
    }

    float4 ra, rb[2];
    ra = *(const float4*)(A + (size_t)akk * lda + m0 + ag * 4);
#pragma unroll
    for (int i = 0; i < 2; i++)
        rb[i] = *(const float4*)(Bm + (size_t)bkk[i] * N + n0 + bng[i] * 4);

    int cur = 0;
    for (int k0 = 0; k0 < K; k0 += 16) {
        *(float4*)&As[cur][akk][ag * 4] = ra;
#pragma unroll
        for (int i = 0; i < 2; i++)
            *(float4*)&Bs[cur][bkk[i]][bng[i] * 4] = rb[i];
        __syncthreads();
        if (k0 + 16 < K) {
            ra = *(const float4*)(A + (size_t)(k0 + 16 + akk) * lda + m0 + ag * 4);
#pragma unroll
            for (int i = 0; i < 2; i++)
                rb[i] = *(const float4*)(Bm + (size_t)(k0 + 16 + bkk[i]) * N + n0 + bng[i] * 4);
        }
#pragma unroll
        for (int kk = 0; kk < 16; kk++) {
            float4 a = *(float4*)&As[cur][kk][ty * 4];
            float4 b0 = *(float4*)&Bs[cur][kk][tx * 8];
            float4 b1 = *(float4*)&Bs[cur][kk][tx * 8 + 4];
            ull bp0 = pk2(b0.x, b0.y), bp1 = pk2(b0.z, b0.w);
            ull bp2 = pk2(b1.x, b1.y), bp3 = pk2(b1.z, b1.w);
            float av[4] = {a.x, a.y, a.z, a.w};
#pragma unroll
            for (int i = 0; i < 4; i++) {
                ull ad = pk2(av[i], av[i]);
                ffma2(acc[i][0], ad, bp0);
                ffma2(acc[i][1], ad, bp1);
                ffma2(acc[i][2], ad, bp2);
                ffma2(acc[i][3], ad, bp3);
            }
        }
        cur ^= 1;
    }
#pragma unroll
    for (int i = 0; i < 4; i++) {
        int row = m0 + ty * 4 + i;
        float2 v0 = up2(acc[i][0]), v1 = up2(acc[i][1]);
        float2 v2 = up2(acc[i][2]), v3 = up2(acc[i][3]);
        float4 o0 = make_float4(v0.x, v0.y, v1.x, v1.y);
        float4 o1 = make_float4(v2.x, v2.y, v3.x, v3.y);
        *(float4*)(C + (size_t)row * N + n0 + tx * 8) = o0;
        *(float4*)(C + (size_t)row * N + n0 + tx * 8 + 4) = o1;
    }
}

// ---------------- 4) sequential scan (R2 skeleton + fast_tanh) --------------
// One CTA per batch, 256 threads = 8 warps.
// Warp w: k-slice ks = w>>1 (64 k values), output half oh = w&1.
// Lane l: 4 outputs u0 = oh*128 + l*4 .. +3.
// Per output: 32 weight pairs over its k-slice; 26 in RF, 6 in SMEM.
// Partial sums part[4][256]; two barriers per step.
#define RF_PAIRS 26
#define SM_PAIRS 6
#define WS_ULLS (SM_PAIRS * 4 * 4 * 64)          // 6144 ull = 48 KB
#define SCAN_SMEM_BYTES (WS_ULLS * 8 + 4 * 256 * 4 + 2 * 256 * 4)

__global__ __launch_bounds__(256, 1) void scan_kernel(const float* __restrict__ Wh,
                                                      const float* __restrict__ xproj,
                                                      const float* __restrict__ bias,
                                                      float* __restrict__ out) {
    extern __shared__ unsigned char smraw[];
    ull* ws = (ull*)smraw;                                  // 48 KB weights
    float* part = (float*)(smraw + WS_ULLS * 8);            // 4 KB partials
    float* hbuf = part + 4 * 256;                           // 2 KB h (double buf)

    const int tid = threadIdx.x;
    const int b = blockIdx.x;
    const int w = tid >> 5, l = tid & 31;
    const int ks = w >> 1, oh = w & 1;
    const int u0 = oh * 128 + l * 4;

    for (int idx = tid; idx < WS_ULLS; idx += 256) {
        int e = idx >> 6, r = idx & 63;
        int ps = e >> 4, ksf = (e >> 2) & 3, jf = e & 3;
        int ohf = r >> 5, lf = r & 31;
        int uf = ohf * 128 + lf * 4 + jf;
        int kf = ksf * 64 + 2 * (RF_PAIRS + ps);
        ws[idx] = pk2(Wh[kf * U_ + uf], Wh[(kf + 1) * U_ + uf]);
    }

    ull wreg[4][RF_PAIRS];
#pragma unroll
    for (int j = 0; j < 4; j++)
#pragma unroll
        for (int p = 0; p < RF_PAIRS; p++) {
            int k = ks * 64 + 2 * p;
            wreg[j][p] = pk2(Wh[k * U_ + u0 + j], Wh[(k + 1) * U_ + u0 + j]);
        }

    hbuf[tid] = 0.f;
    hbuf[256 + tid] = 0.f;
    const float bv = bias[tid];
    __syncthreads();

    const float* xp = xproj + (size_t)b * L_ * U_ + tid;
    float* op = out + (size_t)b * L_ * U_ + tid;
    float xv = xp[0];
    int cur = 0;

    const ull* wsp = ws + ks * 256 + oh * 32 + l;

    for (int s = 0; s < L_; s++) {
        // issue next-step x load early: full step of latency slack
        int sn = (s + 1 < L_) ? s + 1 : s;
        float xn = __ldg(xp + (size_t)sn * U_);

        const ulonglong2* hp2 = (const ulonglong2*)(hbuf + cur * 256 + ks * 64);
        ull a0 = 0ull, a1 = 0ull, a2 = 0ull, a3 = 0ull;
#pragma unroll
        for (int q = 0; q < 13; q++) {   // pairs 0..25 (RF)
            ulonglong2 hv = hp2[q];
            ffma2(a0, hv.x, wreg[0][2 * q]);
            ffma2(a1, hv.x, wreg[1][2 * q]);
            ffma2(a2, hv.x, wreg[2][2 * q]);
            ffma2(a3, hv.x, wreg[3][2 * q]);
            ffma2(a0, hv.y, wreg[0][2 * q + 1]);
            ffma2(a1, hv.y, wreg[1][2 * q + 1]);
            ffma2(a2, hv.y, wreg[2][2 * q + 1]);
            ffma2(a3, hv.y, wreg[3][2 * q + 1]);
        }
#pragma unroll
        for (int qq = 0; qq < 3; qq++) { // pairs 26..31 (SMEM)
            ulonglong2 hv = hp2[13 + qq];
            int ps0 = 2 * qq, ps1 = 2 * qq + 1;
            ffma2(a0, hv.x, wsp[ps0 * 1024 + 0 * 64]);
            ffma2(a1, hv.x, wsp[ps0 * 1024 + 1 * 64]);
            ffma2(a2, hv.x, wsp[ps0 * 1024 + 2 * 64]);
            ffma2(a3, hv.x, wsp[ps0 * 1024 + 3 * 64]);
            ffma2(a0, hv.y, wsp[ps1 * 1024 + 0 * 64]);
            ffma2(a1, hv.y, wsp[ps1 * 1024 + 1 * 64]);
            ffma2(a2, hv.y, wsp[ps1 * 1024 + 2 * 64]);
            ffma2(a3, hv.y, wsp[ps1 * 1024 + 3 * 64]);
        }
        float2 v0 = up2(a0), v1 = up2(a1), v2 = up2(a2), v3 = up2(a3);
        float4 pr = make_float4(v0.x + v0.y, v1.x + v1.y, v2.x + v2.y, v3.x + v3.y);
        *(float4*)&part[ks * 256 + u0] = pr;
        __syncthreads();

        float z = part[tid] + part[256 + tid] + part[512 + tid] + part[768 + tid]
                  + xv + bv;
        float h = fast_tanh(z);
        hbuf[(cur ^ 1) * 256 + tid] = h;
        op[(size_t)s * U_] = h;
        xv = xn;
        cur ^= 1;
        __syncthreads();
    }
}

// ---------------- launch --------------------------------------------------
extern "C" void kernel_launch(void* const* d_in, const int* in_sizes, int n_in,
                              void* d_out, int out_size) {
    const float* seq = (const float*)d_in[0];    // (8,1024,256)
    const float* graph = (const float*)d_in[1];  // (8,1024,1024)
    const float* E = (const float*)d_in[2];      // (256,256)
    const float* Wx = (const float*)d_in[3];     // (256,256)
    const float* Wh = (const float*)d_in[4];     // (256,256)
    const float* bias = (const float*)d_in[5];   // (256,)
    float* out = (float*)d_out;                  // (8,1024,256)

    float *ew, *rn, *tt, *xp;
    cudaGetSymbolAddress((void**)&ew, g_EW);
    cudaGetSymbolAddress((void**)&rn, g_rnorm);
    cudaGetSymbolAddress((void**)&tt, g_t);
    cudaGetSymbolAddress((void**)&xp, g_xproj);

    norm_kernel<<<(B_ * L_) / 8, 256>>>(graph, rn);
    // EW = E @ Wx (256x256x256)
    gemm_nn<<<dim3(2, 4), 256>>>(E, Wx, ew, 256, nullptr);
    // t = (seq @ EW) * rnorm   (M=8192)
    gemm_nn<<<dim3(2, 128), 256>>>(seq, ew, tt, 256, rn);
    // xproj[b] = G[b]^T @ t[b] (per batch M=1024, K=1024)
    gemm_tn<<<dim3(2, 16, 8), 256>>>(graph, tt, xp);
    cudaFuncSetAttribute(scan_kernel, cudaFuncAttributeMaxDynamicSharedMemorySize,
                         SCAN_SMEM_BYTES);
    scan_kernel<<<B_, 256, SCAN_SMEM_BYTES>>>(Wh, xp, bias, out);
}